// round 16
// baseline (speedup 1.0000x reference)
#include <cuda_runtime.h>
#include <cuda_bf16.h>

#define CROP 81
#define PIX  (CROP * CROP)        // 6561
#define SPLIT 3                   // 27 rows per block
#define THREADS 256               // 243 active (3 groups x 81 cols)

// One block = one (n,p) crop, 27 output rows. Each thread owns a fixed
// column j and 9 consecutive rows (3 chunks of 3, boundary hl carried in
// registers: 10 image rows / 9 outputs). NO shared memory, NO barrier:
// every thread computes its own x-entry and per-chunk y-entries directly
// (exact reference float chain), overlapping that ALU with load latency.
__global__ __launch_bounds__(THREADS)
void selectnet_kernel(const float* __restrict__ img,
                      const int*   __restrict__ label,
                      const float* __restrict__ points,
                      float*       __restrict__ out,
                      int N)
{
    const int W = 512, H = 512;
    const size_t plane = (size_t)H * W;

    const int q = blockIdx.x;       // n*6 + p
    const int p = q % 6;
    const int n = q / 6;
    const int t = threadIdx.x;
    if (t >= 3 * CROP) return;

    const int g = t / CROP;            // 0..2
    const int j = t - g * CROP;        // 0..80
    const int i0 = blockIdx.y * 27 + g * 9;

    // ---- exact replication of reference float32 op chain ----
    const float* pt = points + (size_t)n * 18;
    float py, px;
    if (p < 5) {
        py = pt[(p + 1) * 2 + 0];
        px = pt[(p + 1) * 2 + 1];
    } else {
        py = __fdiv_rn(__fadd_rn(__fadd_rn(pt[12], pt[14]), pt[16]), 3.0f);
        px = __fdiv_rn(__fadd_rn(__fadd_rn(pt[13], pt[15]), pt[17]), 3.0f);
    }
    const float fw = 511.0f, fh = 511.0f;
    const float sx = (float)(80.0 / 511.0);   // (CROP-1)/(W-1)
    const float sy = (float)(80.0 / 512.0);   // (CROP-1)/H  (reference asymmetry)
    const float delta = __fdiv_rn(2.0f, 80.0f);

    const float tx = __fadd_rn(-1.0f, __fdiv_rn(__fmul_rn(2.0f, px), fw));
    const float ty = __fadd_rn(-1.0f, __fdiv_rn(__fmul_rn(2.0f, py), fh));

    // ---- x entry for column j (registers) ----
    float basej = __fadd_rn(-1.0f, __fmul_rn((float)j, delta));
    float gx = __fadd_rn(__fmul_rn(sx, basej), tx);
    float ix = __fmul_rn(__fmul_rn(__fadd_rn(gx, 1.0f), 0.5f), fw);
    float x0f = floorf(ix);
    float wx1v = ix - x0f;
    int x0 = (int)x0f, x1 = x0 + 1;
    const float wx0 = (x0 >= 0 && x0 <= W - 1) ? (1.0f - wx1v) : 0.0f;
    const float wx1 = (x1 >= 0 && x1 <= W - 1) ? wx1v : 0.0f;
    const int c0 = min(max(x0, 0), W - 1);
    const int c1 = min(max(x1, 0), W - 1);
    float xr = rintf(ix);
    const int lx = (xr >= 0.0f && xr <= fw) ? (int)xr : -1;

    // ---- per-row y entry (registers), exact chain ----
    auto yrow = [&](int i, float& wy0, float& wy1, int& y0raw, int& lyrow) {
        float basei = __fadd_rn(-1.0f, __fmul_rn((float)i, delta));
        float gy = __fadd_rn(__fmul_rn(sy, basei), ty);
        float iy = __fmul_rn(__fmul_rn(__fadd_rn(gy, 1.0f), 0.5f), fh);
        float y0f = floorf(iy);
        float wy1v = iy - y0f;
        int y0 = (int)y0f, y1 = y0 + 1;
        wy0 = (y0 >= 0 && y0 <= H - 1) ? (1.0f - wy1v) : 0.0f;
        wy1 = (y1 >= 0 && y1 <= H - 1) ? wy1v : 0.0f;
        float yr = rintf(iy);
        lyrow = (yr >= 0.0f && yr <= fh) ? (((int)yr) << 9) : -1;
        y0raw = y0;
    };

    const float* imgn = img   + (size_t)n * 3 * plane;
    const int*   labn = label + (size_t)n * plane;
    float*       outq  = out + (size_t)q * 3 * PIX + (size_t)i0 * CROP + j;
    float*       predq = out + (size_t)N * 6 * 3 * PIX + (size_t)q * PIX + (size_t)i0 * CROP + j;
    const int target = p + 1;

    auto predf = [&](int lab) -> float {
        if (p < 5) return (lab == target) ? 1.0f : 0.0f;
        return (lab == 6) ? 1.0f : (lab == 7) ? 2.0f : (lab == 8) ? 3.0f : 0.0f;
    };

    // first row's y entry gives base0 (address anchor for all 10 window rows)
    float wyA0, wyA1; int y0rA, lyrA;
    yrow(i0, wyA0, wyA1, y0rA, lyrA);
    const int base0 = y0rA;

    float hp2[3], hp1[3];   // per-channel carries: hl[3m-1], hl[3m]

    // ================= chunk 0 (rows 0..2, window rows 0..3) =================
    {
        int ro0 = min(max(base0 + 0, 0), H - 1) << 9;
        int ro1 = min(max(base0 + 1, 0), H - 1) << 9;
        int ro2 = min(max(base0 + 2, 0), H - 1) << 9;
        int ro3 = min(max(base0 + 3, 0), H - 1) << 9;

        // y entries for rows 1,2 (overlap with load latency)
        float wyB0, wyB1; int y0rB, lyrB;
        float wyC0, wyC1; int y0rC, lyrC;
        yrow(i0 + 1, wyB0, wyB1, y0rB, lyrB);
        yrow(i0 + 2, wyC0, wyC1, y0rC, lyrC);
        bool pb = (y0rB - base0) == 1;
        bool pc = (y0rC - base0) == 2;

        int la0 = ((lx | lyrA) >= 0) ? __ldg(labn + lyrA + lx) : 0;
        int la1 = ((lx | lyrB) >= 0) ? __ldg(labn + lyrB + lx) : 0;
        int la2 = ((lx | lyrC) >= 0) ? __ldg(labn + lyrC + lx) : 0;

        #pragma unroll
        for (int c = 0; c < 3; ++c) {
            const float* cp = imgn + (size_t)c * plane;
            float a0 = __ldg(cp + ro0 + c0), b0 = __ldg(cp + ro0 + c1);
            float a1 = __ldg(cp + ro1 + c0), b1 = __ldg(cp + ro1 + c1);
            float a2 = __ldg(cp + ro2 + c0), b2 = __ldg(cp + ro2 + c1);
            float a3 = __ldg(cp + ro3 + c0), b3 = __ldg(cp + ro3 + c1);

            float h0 = a0 * wx0 + b0 * wx1;
            float h1 = a1 * wx0 + b1 * wx1;
            float h2 = a2 * wx0 + b2 * wx1;
            float h3 = a3 * wx0 + b3 * wx1;

            float o0 = h0 * wyA0 + h1 * wyA1;
            float o1 = (pb ? h1 : h0) * wyB0 + (pb ? h2 : h1) * wyB1;
            float o2 = (pc ? h2 : h1) * wyC0 + (pc ? h3 : h2) * wyC1;

            float* op = outq + (size_t)c * PIX;
            __stcs(op + 0 * CROP, o0);
            __stcs(op + 1 * CROP, o1);
            __stcs(op + 2 * CROP, o2);
            hp2[c] = h2; hp1[c] = h3;
        }

        __stcs(predq + 0 * CROP, predf(la0));
        __stcs(predq + 1 * CROP, predf(la1));
        __stcs(predq + 2 * CROP, predf(la2));
    }

    // ========== chunks m = 1,2 (rows 3m..3m+2, new window rows 3m+1..3m+3) =======
    #pragma unroll
    for (int m = 1; m < 3; ++m) {
        const int k0 = 3 * m;

        int roA = min(max(base0 + k0 + 1, 0), H - 1) << 9;
        int roB = min(max(base0 + k0 + 2, 0), H - 1) << 9;
        int roC = min(max(base0 + k0 + 3, 0), H - 1) << 9;

        float wy00, wy01; int y0r0, lyr0;
        float wy10, wy11; int y0r1, lyr1;
        float wy20, wy21; int y0r2, lyr2;
        yrow(i0 + k0 + 0, wy00, wy01, y0r0, lyr0);
        yrow(i0 + k0 + 1, wy10, wy11, y0r1, lyr1);
        yrow(i0 + k0 + 2, wy20, wy21, y0r2, lyr2);
        bool pa = (y0r0 - base0) == k0;
        bool pb = (y0r1 - base0) == k0 + 1;
        bool pc = (y0r2 - base0) == k0 + 2;

        int la0 = ((lx | lyr0) >= 0) ? __ldg(labn + lyr0 + lx) : 0;
        int la1 = ((lx | lyr1) >= 0) ? __ldg(labn + lyr1 + lx) : 0;
        int la2 = ((lx | lyr2) >= 0) ? __ldg(labn + lyr2 + lx) : 0;

        #pragma unroll
        for (int c = 0; c < 3; ++c) {
            const float* cp = imgn + (size_t)c * plane;
            float aA = __ldg(cp + roA + c0), bA = __ldg(cp + roA + c1);
            float aB = __ldg(cp + roB + c0), bB = __ldg(cp + roB + c1);
            float aC = __ldg(cp + roC + c0), bC = __ldg(cp + roC + c1);

            float h1 = aA * wx0 + bA * wx1;     // hl[k0+1]
            float h2 = aB * wx0 + bB * wx1;     // hl[k0+2]
            float h3 = aC * wx0 + bC * wx1;     // hl[k0+3]
            float m1 = hp1[c], m2 = hp2[c];     // hl[k0], hl[k0-1]

            float o0 = (pa ? m1 : m2) * wy00 + (pa ? h1 : m1) * wy01;
            float o1 = (pb ? h1 : m1) * wy10 + (pb ? h2 : h1) * wy11;
            float o2 = (pc ? h2 : h1) * wy20 + (pc ? h3 : h2) * wy21;

            float* op = outq + (size_t)c * PIX + (size_t)k0 * CROP;
            __stcs(op + 0 * CROP, o0);
            __stcs(op + 1 * CROP, o1);
            __stcs(op + 2 * CROP, o2);
            hp2[c] = h2; hp1[c] = h3;
        }

        float* pp = predq + (size_t)k0 * CROP;
        __stcs(pp + 0 * CROP, predf(la0));
        __stcs(pp + 1 * CROP, predf(la1));
        __stcs(pp + 2 * CROP, predf(la2));
    }
}

extern "C" void kernel_launch(void* const* d_in, const int* in_sizes, int n_in,
                              void* d_out, int out_size) {
    const float* img    = (const float*)d_in[0];   // (N, 3, 512, 512) f32
    const int*   label  = (const int*)  d_in[1];   // (N, 512, 512) i32
    const float* points = (const float*)d_in[2];   // (N, 9, 2) f32
    float* out = (float*)d_out;

    int N = in_sizes[2] / 18;                      // points = N*9*2

    dim3 grid(N * 6, SPLIT);
    selectnet_kernel<<<grid, THREADS>>>(img, label, points, out, N);
}

// round 17
// speedup vs baseline: 1.0118x; 1.0118x over previous
#include <cuda_runtime.h>
#include <cuda_bf16.h>

#define CROP 81
#define PIX  (CROP * CROP)        // 6561
#define SPLIT 3                   // 27 rows per block
#define THREADS 256               // 243 active (3 groups x 81 cols)

// R12 structure (9 rows/thread, 3 chunks, boundary hl carried, __stcs) with:
//  - prologue split across warps (x-table: t in [0,81), y-table: t in [96,177))
//  - all 9 label loads hoisted ahead of the image chunks
__global__ __launch_bounds__(THREADS)
void selectnet_kernel(const float* __restrict__ img,
                      const int*   __restrict__ label,
                      const float* __restrict__ points,
                      float*       __restrict__ out,
                      int N)
{
    const int W = 512, H = 512;
    const size_t plane = (size_t)H * W;

    // x: (wx0, wx1, bits[c0 | c1<<9 | (lx+1)<<18], 0)
    // y: (wy0, wy1, bits[y0 raw unclamped], bits[lyrow or -1])
    __shared__ float4 sxt[CROP];
    __shared__ float4 syt[CROP];

    const int q = blockIdx.x;       // n*6 + p
    const int p = q % 6;
    const int n = q / 6;
    const int t = threadIdx.x;

    // ---- prologue: two disjoint warp-groups build the two tables in parallel
    const bool doX = (t < CROP);
    const bool doY = (t >= 96) && (t < 96 + CROP);
    if (doX || doY) {
        const int e = doX ? t : (t - 96);    // table index
        // ---- exact replication of reference float32 op chain ----
        const float* pt = points + (size_t)n * 18;
        float py, px;
        if (p < 5) {
            py = pt[(p + 1) * 2 + 0];
            px = pt[(p + 1) * 2 + 1];
        } else {
            py = __fdiv_rn(__fadd_rn(__fadd_rn(pt[12], pt[14]), pt[16]), 3.0f);
            px = __fdiv_rn(__fadd_rn(__fadd_rn(pt[13], pt[15]), pt[17]), 3.0f);
        }
        const float fw = 511.0f, fh = 511.0f;
        const float sx = (float)(80.0 / 511.0);   // (CROP-1)/(W-1)
        const float sy = (float)(80.0 / 512.0);   // (CROP-1)/H  (reference asymmetry)
        const float delta = __fdiv_rn(2.0f, 80.0f);
        float base = __fadd_rn(-1.0f, __fmul_rn((float)e, delta));

        if (doX) {
            float tx = __fadd_rn(-1.0f, __fdiv_rn(__fmul_rn(2.0f, px), fw));
            float gx = __fadd_rn(__fmul_rn(sx, base), tx);
            float ix = __fmul_rn(__fmul_rn(__fadd_rn(gx, 1.0f), 0.5f), fw);
            float x0f = floorf(ix);
            float wx1v = ix - x0f;
            int x0 = (int)x0f, x1 = x0 + 1;
            float wx0 = (x0 >= 0 && x0 <= W - 1) ? (1.0f - wx1v) : 0.0f;
            float wx1 = (x1 >= 0 && x1 <= W - 1) ? wx1v : 0.0f;
            int c0 = min(max(x0, 0), W - 1);
            int c1 = min(max(x1, 0), W - 1);
            float xr = rintf(ix);
            int lx = (xr >= 0.0f && xr <= fw) ? (int)xr : -1;
            sxt[e] = make_float4(wx0, wx1,
                                 __int_as_float(c0 | (c1 << 9) | ((lx + 1) << 18)), 0.0f);
        } else {
            float ty = __fadd_rn(-1.0f, __fdiv_rn(__fmul_rn(2.0f, py), fh));
            float gy = __fadd_rn(__fmul_rn(sy, base), ty);
            float iy = __fmul_rn(__fmul_rn(__fadd_rn(gy, 1.0f), 0.5f), fh);
            float y0f = floorf(iy);
            float wy1v = iy - y0f;
            int y0 = (int)y0f, y1 = y0 + 1;
            float wy0 = (y0 >= 0 && y0 <= H - 1) ? (1.0f - wy1v) : 0.0f;
            float wy1 = (y1 >= 0 && y1 <= H - 1) ? wy1v : 0.0f;
            float yr = rintf(iy);
            int lyrow = (yr >= 0.0f && yr <= fh) ? ((int)yr) * W : -1;
            syt[e] = make_float4(wy0, wy1, __int_as_float(y0), __int_as_float(lyrow));
        }
    }
    __syncthreads();

    if (t >= 3 * CROP) return;
    const int g = t / CROP;            // 0..2
    const int j = t - g * CROP;        // 0..80
    const int i0 = blockIdx.y * 27 + g * 9;

    float4 xt = sxt[j];
    int xp = __float_as_int(xt.z);
    const int c0 = xp & 511, c1 = (xp >> 9) & 511, lx = (xp >> 18) - 1;

    const float* imgn = img   + (size_t)n * 3 * plane;
    const int*   labn = label + (size_t)n * plane;
    float*       outq  = out + (size_t)q * 3 * PIX + (size_t)i0 * CROP + j;
    float*       predq = out + (size_t)N * 6 * 3 * PIX + (size_t)q * PIX + (size_t)i0 * CROP + j;
    const int target = p + 1;

    const int base0 = __float_as_int(syt[i0].z);   // raw y0 of first row

    // ---- hoisted: ALL 9 label loads, batched before image chunks ----
    int la[9];
    #pragma unroll
    for (int k = 0; k < 9; ++k) {
        int lyr = __float_as_int(syt[i0 + k].w);
        la[k] = ((lx | lyr) >= 0) ? __ldg(labn + lyr + lx) : 0;
    }

    auto predf = [&](int lab) -> float {
        if (p < 5) return (lab == target) ? 1.0f : 0.0f;
        return (lab == 6) ? 1.0f : (lab == 7) ? 2.0f : (lab == 8) ? 3.0f : 0.0f;
    };

    float hp2[3], hp1[3];   // per-channel carries: hl[3m-1], hl[3m]

    // ================= chunk 0 (rows 0..2, window rows 0..3) =================
    {
        float4 ya = syt[i0], yb = syt[i0 + 1], yc = syt[i0 + 2];
        bool pb = (__float_as_int(yb.z) - base0) == 1;
        bool pc = (__float_as_int(yc.z) - base0) == 2;

        int ro0 = min(max(base0 + 0, 0), H - 1) << 9;
        int ro1 = min(max(base0 + 1, 0), H - 1) << 9;
        int ro2 = min(max(base0 + 2, 0), H - 1) << 9;
        int ro3 = min(max(base0 + 3, 0), H - 1) << 9;

        #pragma unroll
        for (int c = 0; c < 3; ++c) {
            const float* cp = imgn + (size_t)c * plane;
            float a0 = __ldg(cp + ro0 + c0), b0 = __ldg(cp + ro0 + c1);
            float a1 = __ldg(cp + ro1 + c0), b1 = __ldg(cp + ro1 + c1);
            float a2 = __ldg(cp + ro2 + c0), b2 = __ldg(cp + ro2 + c1);
            float a3 = __ldg(cp + ro3 + c0), b3 = __ldg(cp + ro3 + c1);

            float h0 = a0 * xt.x + b0 * xt.y;
            float h1 = a1 * xt.x + b1 * xt.y;
            float h2 = a2 * xt.x + b2 * xt.y;
            float h3 = a3 * xt.x + b3 * xt.y;

            float o0 = h0 * ya.x + h1 * ya.y;
            float o1 = (pb ? h1 : h0) * yb.x + (pb ? h2 : h1) * yb.y;
            float o2 = (pc ? h2 : h1) * yc.x + (pc ? h3 : h2) * yc.y;

            float* op = outq + (size_t)c * PIX;
            __stcs(op + 0 * CROP, o0);
            __stcs(op + 1 * CROP, o1);
            __stcs(op + 2 * CROP, o2);
            hp2[c] = h2; hp1[c] = h3;
        }

        __stcs(predq + 0 * CROP, predf(la[0]));
        __stcs(predq + 1 * CROP, predf(la[1]));
        __stcs(predq + 2 * CROP, predf(la[2]));
    }

    // ========== chunks m = 1,2 (rows 3m..3m+2, new window rows 3m+1..3m+3) =======
    #pragma unroll
    for (int m = 1; m < 3; ++m) {
        const int k0 = 3 * m;
        float4 ya = syt[i0 + k0], yb = syt[i0 + k0 + 1], yc = syt[i0 + k0 + 2];
        bool pa = (__float_as_int(ya.z) - base0) == k0;
        bool pb = (__float_as_int(yb.z) - base0) == k0 + 1;
        bool pc = (__float_as_int(yc.z) - base0) == k0 + 2;

        int roA = min(max(base0 + k0 + 1, 0), H - 1) << 9;
        int roB = min(max(base0 + k0 + 2, 0), H - 1) << 9;
        int roC = min(max(base0 + k0 + 3, 0), H - 1) << 9;

        #pragma unroll
        for (int c = 0; c < 3; ++c) {
            const float* cp = imgn + (size_t)c * plane;
            float aA = __ldg(cp + roA + c0), bA = __ldg(cp + roA + c1);
            float aB = __ldg(cp + roB + c0), bB = __ldg(cp + roB + c1);
            float aC = __ldg(cp + roC + c0), bC = __ldg(cp + roC + c1);

            float h1 = aA * xt.x + bA * xt.y;   // hl[k0+1]
            float h2 = aB * xt.x + bB * xt.y;   // hl[k0+2]
            float h3 = aC * xt.x + bC * xt.y;   // hl[k0+3]
            float m1 = hp1[c], m2 = hp2[c];     // hl[k0], hl[k0-1]

            float o0 = (pa ? m1 : m2) * ya.x + (pa ? h1 : m1) * ya.y;
            float o1 = (pb ? h1 : m1) * yb.x + (pb ? h2 : h1) * yb.y;
            float o2 = (pc ? h2 : h1) * yc.x + (pc ? h3 : h2) * yc.y;

            float* op = outq + (size_t)c * PIX + (size_t)k0 * CROP;
            __stcs(op + 0 * CROP, o0);
            __stcs(op + 1 * CROP, o1);
            __stcs(op + 2 * CROP, o2);
            hp2[c] = h2; hp1[c] = h3;
        }

        float* pp = predq + (size_t)k0 * CROP;
        __stcs(pp + 0 * CROP, predf(la[k0 + 0]));
        __stcs(pp + 1 * CROP, predf(la[k0 + 1]));
        __stcs(pp + 2 * CROP, predf(la[k0 + 2]));
    }
}

extern "C" void kernel_launch(void* const* d_in, const int* in_sizes, int n_in,
                              void* d_out, int out_size) {
    const float* img    = (const float*)d_in[0];   // (N, 3, 512, 512) f32
    const int*   label  = (const int*)  d_in[1];   // (N, 512, 512) i32
    const float* points = (const float*)d_in[2];   // (N, 9, 2) f32
    float* out = (float*)d_out;

    int N = in_sizes[2] / 18;                      // points = N*9*2

    dim3 grid(N * 6, SPLIT);
    selectnet_kernel<<<grid, THREADS>>>(img, label, points, out, N);
}